// round 12
// baseline (speedup 1.0000x reference)
#include <cuda_runtime.h>
#include <math.h>

#define T_TOK  8192
#define D_DIM  4096
#define E_EXP  64
#define BM     64
#define BK     32
#define NTHR   256
#define TOPK   8

__global__ __launch_bounds__(NTHR, 1)
void router_kernel(const float* __restrict__ x,   // [T, D]
                   const float* __restrict__ w,   // [D, E]
                   float* __restrict__ out,
                   int out_size)
{
    __shared__ float xs[BM][BK + 4];
    __shared__ float ws[BK][E_EXP];
    __shared__ float logits[BM][E_EXP + 1];

    const int tid  = threadIdx.x;
    const int tx   = tid & 15;
    const int ty   = tid >> 4;
    const int row0 = blockIdx.x * BM;

    // contiguous split-8 (Eigen kc=512 panel hypothesis):
    // eight 512-k panels, serial ascending FMA within a panel, panels folded
    // ascending into the running total.
    float tot[4][4];
    float cha[4][4];
#pragma unroll
    for (int i = 0; i < 4; ++i)
#pragma unroll
        for (int j = 0; j < 4; ++j) { tot[i][j] = 0.0f; cha[i][j] = 0.0f; }

    const int sx0 = tid, sx1 = tid + 256;
    const int xm0 = sx0 >> 3, xq0 = sx0 & 7;
    const int xm1 = sx1 >> 3, xq1 = sx1 & 7;
    const int wk0 = tid >> 4;
    const int weq = tid & 15;

    const float* xbase = x + (size_t)row0 * D_DIM;

    float4 xr0 = *(const float4*)(xbase + xm0 * D_DIM + xq0 * 4);
    float4 xr1 = *(const float4*)(xbase + xm1 * D_DIM + xq1 * 4);
    float4 wr0 = *(const float4*)(w + (size_t)wk0        * E_EXP + weq * 4);
    float4 wr1 = *(const float4*)(w + (size_t)(wk0 + 16) * E_EXP + weq * 4);

    const int NCHUNK = D_DIM / BK;   // 128 chunks; 16 chunks = one 512-k panel
    for (int c = 0; c < NCHUNK; ++c) {
        *(float4*)&xs[xm0][xq0 * 4] = xr0;
        *(float4*)&xs[xm1][xq1 * 4] = xr1;
        *(float4*)&ws[wk0][weq * 4]      = wr0;
        *(float4*)&ws[wk0 + 16][weq * 4] = wr1;
        __syncthreads();

        if (c + 1 < NCHUNK) {
            const int c0 = (c + 1) * BK;
            xr0 = *(const float4*)(xbase + xm0 * D_DIM + c0 + xq0 * 4);
            xr1 = *(const float4*)(xbase + xm1 * D_DIM + c0 + xq1 * 4);
            wr0 = *(const float4*)(w + (size_t)(c0 + wk0)      * E_EXP + weq * 4);
            wr1 = *(const float4*)(w + (size_t)(c0 + wk0 + 16) * E_EXP + weq * 4);
        }

        // serial ascending fp32 FMA within the current panel
#pragma unroll 8
        for (int k = 0; k < BK; ++k) {
            const float4 wv = *(const float4*)&ws[k][tx * 4];
            const float xv0 = xs[ty * 4 + 0][k];
            const float xv1 = xs[ty * 4 + 1][k];
            const float xv2 = xs[ty * 4 + 2][k];
            const float xv3 = xs[ty * 4 + 3][k];
            cha[0][0] += xv0 * wv.x; cha[0][1] += xv0 * wv.y;
            cha[0][2] += xv0 * wv.z; cha[0][3] += xv0 * wv.w;
            cha[1][0] += xv1 * wv.x; cha[1][1] += xv1 * wv.y;
            cha[1][2] += xv1 * wv.z; cha[1][3] += xv1 * wv.w;
            cha[2][0] += xv2 * wv.x; cha[2][1] += xv2 * wv.y;
            cha[2][2] += xv2 * wv.z; cha[2][3] += xv2 * wv.w;
            cha[3][0] += xv3 * wv.x; cha[3][1] += xv3 * wv.y;
            cha[3][2] += xv3 * wv.z; cha[3][3] += xv3 * wv.w;
        }

        // end of a 512-k panel: fold panel sum into total (ascending), reset
        if ((c & 15) == 15) {
#pragma unroll
            for (int i = 0; i < 4; ++i)
#pragma unroll
                for (int j = 0; j < 4; ++j) {
                    tot[i][j] += cha[i][j];
                    cha[i][j] = 0.0f;
                }
        }
        __syncthreads();
    }

#pragma unroll
    for (int i = 0; i < 4; ++i)
#pragma unroll
        for (int j = 0; j < 4; ++j)
            logits[ty * 4 + i][tx * 4 + j] = tot[i][j];
    __syncthreads();

    // ---- top-8 + softmax: one thread per token ----
    if (tid < BM) {
        const float* rowv = &logits[tid][0];
        unsigned long long used = 0ull;
        float vals[TOPK];
        int   idx[TOPK];
#pragma unroll
        for (int s = 0; s < TOPK; ++s) {
            float best = -INFINITY;
            int   bi   = 0;
            for (int e = 0; e < E_EXP; ++e) {
                if (!((used >> e) & 1ull)) {
                    float v = rowv[e];
                    if (v > best) { best = v; bi = e; }
                }
            }
            used |= 1ull << bi;
            vals[s] = best;
            idx[s]  = bi;
        }
        const float mx = vals[0];
        float ev[TOPK];
        float sum = 0.0f;
#pragma unroll
        for (int s = 0; s < TOPK; ++s) { ev[s] = expf(vals[s] - mx); sum += ev[s]; }
        const float inv = 1.0f / sum;

        const int token = row0 + tid;
        float* wout = out + (size_t)token * TOPK;
#pragma unroll
        for (int s = 0; s < TOPK; ++s) wout[s] = ev[s] * inv;

        if (out_size >= T_TOK * TOPK * 2) {
            float* eout = out + (size_t)T_TOK * TOPK + (size_t)token * TOPK;
#pragma unroll
            for (int s = 0; s < TOPK; ++s) eout[s] = (float)idx[s];
        }
    }
}

extern "C" void kernel_launch(void* const* d_in, const int* in_sizes, int n_in,
                              void* d_out, int out_size)
{
    const float* a = (const float*)d_in[0];
    const float* b = (const float*)d_in[1];
    const float* x = a;
    const float* w = b;
    if (n_in >= 2 && in_sizes[0] == D_DIM * E_EXP && in_sizes[1] == T_TOK * D_DIM) {
        x = b; w = a;
    }
    router_kernel<<<T_TOK / BM, NTHR>>>(x, w, (float*)d_out, out_size);
}